// round 15
// baseline (speedup 1.0000x reference)
#include <cuda_runtime.h>
#include <cuda_fp16.h>
#include <math.h>
#include <stdint.h>

#define BATCH 16
#define SEQ   1024
#define DM    256
#define FF    1024
#define NH    8
#define HDIM  32
#define ROWS  (BATCH*SEQ)   // 16384

#define QSCALE 0.09016844005555556f   // D^-0.5 * log2e
#define BSHIFT 5.770780163555852f     // 4*log2e

// ---------------- scratch (device globals; no cudaMalloc allowed) ----------
__device__ __half g_attin[ROWS*DM];
__device__ __half g_ffnin[ROWS*DM];
__device__ __half g_qh[ROWS*DM], g_kh[ROWS*DM], g_vh[ROWS*DM];
__device__ __half g_oh[ROWS*DM];
__device__ float  g_attnout[ROWS*DM];
__device__ __half g_hh[ROWS*FF];
__device__ int    g_rowflag[ROWS];
__device__ __half g_bsum[(size_t)BATCH*SEQ*SEQ];   // (half)((sp+ed)*log2e - 4*log2e)
__device__ __half g_wq[DM*DM], g_wk[DM*DM], g_wv[DM*DM], g_wo[DM*DM];
__device__ __half g_w1[FF*DM], g_w2[DM*FF];

static __device__ __forceinline__ uint32_t smem_u32(const void* p){
  uint32_t a;
  asm("{ .reg .u64 t; cvta.to.shared.u64 t, %1; cvt.u32.u64 %0, t; }" : "=r"(a) : "l"(p));
  return a;
}

// ---------------- mma.sync / ldmatrix / cp.async ---------------------------
#define LDSM4(r0,r1,r2,r3,addr) \
  asm volatile("ldmatrix.sync.aligned.m8n8.x4.shared.b16 {%0,%1,%2,%3}, [%4];" \
    : "=r"(r0), "=r"(r1), "=r"(r2), "=r"(r3) : "r"(addr))

#define LDSM4T(r0,r1,r2,r3,addr) \
  asm volatile("ldmatrix.sync.aligned.m8n8.x4.trans.shared.b16 {%0,%1,%2,%3}, [%4];" \
    : "=r"(r0), "=r"(r1), "=r"(r2), "=r"(r3) : "r"(addr))

#define MMAF16(c, a, b) \
  asm volatile("mma.sync.aligned.m16n8k16.row.col.f32.f16.f16.f32 " \
    "{%0,%1,%2,%3},{%4,%5,%6,%7},{%8,%9},{%0,%1,%2,%3};" \
    : "+f"((c)[0]), "+f"((c)[1]), "+f"((c)[2]), "+f"((c)[3]) \
    : "r"((a)[0]), "r"((a)[1]), "r"((a)[2]), "r"((a)[3]), \
      "r"((b)[0]), "r"((b)[1]))

#define MMAF16H(c, a, b) \
  asm volatile("mma.sync.aligned.m16n8k16.row.col.f16.f16.f16.f16 " \
    "{%0,%1},{%2,%3,%4,%5},{%6,%7},{%0,%1};" \
    : "+r"((c)[0]), "+r"((c)[1]) \
    : "r"((a)[0]), "r"((a)[1]), "r"((a)[2]), "r"((a)[3]), \
      "r"((b)[0]), "r"((b)[1]))

#define CPA16(dst, src) \
  asm volatile("cp.async.cg.shared.global [%0], [%1], 16;" :: "r"(dst), "l"(src) : "memory")
#define CPA_COMMIT() asm volatile("cp.async.commit_group;" ::: "memory")
#define CPA_WAIT(n)  asm volatile("cp.async.wait_group %0;" :: "n"(n) : "memory")

static __device__ __forceinline__ uint32_t packh2(float hi, float lo){
  uint32_t r; asm("cvt.rn.f16x2.f32 %0, %1, %2;" : "=r"(r) : "f"(hi), "f"(lo)); return r;
}
static __device__ __forceinline__ uint32_t ex2h2(uint32_t y){
  uint32_t r; asm("ex2.approx.f16x2 %0, %1;" : "=r"(r) : "r"(y)); return r;
}
static __device__ __forceinline__ uint32_t hadd2u(uint32_t a, uint32_t b){
  __half2 r = __hadd2(*(__half2*)&a, *(__half2*)&b); return *(uint32_t*)&r;
}

static __device__ __forceinline__ float gelu_t(float x){
  float x3 = x*x*x;
  float u = 0.7978845608028654f * (x + 0.044715f*x3);
  return 0.5f * x * (1.0f + tanhf(u));
}

// ================== bodies (block coords passed explicitly) =================

// ---- wconv: 768 blocks of 256 thr; blocks <16 also zero rowflag ----
static __device__ void wconv_body(int blk, int tid,
    const float* s0, const float* s1, const float* s2,
    const float* s3, const float* s4, const float* s5)
{
  if (blk < 16)
    ((int4*)g_rowflag)[blk*256 + tid] = make_int4(0,0,0,0);
  int i = (blk*256 + tid)*4;
  const float* src; __half* dst; int off;
  if      (i < 65536)  { src = s0; dst = g_wq; off = i; }
  else if (i < 131072) { src = s1; dst = g_wk; off = i - 65536; }
  else if (i < 196608) { src = s2; dst = g_wv; off = i - 131072; }
  else if (i < 262144) { src = s3; dst = g_wo; off = i - 196608; }
  else if (i < 524288) { src = s4; dst = g_w1; off = i - 262144; }
  else                 { src = s5; dst = g_w2; off = i - 524288; }
  float4 v = *(const float4*)(src + off);
  uint2 o;
  o.x = packh2(v.y, v.x);
  o.y = packh2(v.w, v.z);
  *(uint2*)(dst + off) = o;
}

// ---- LN: one row per block (256 thr) ----
static __device__ void ln_body(int row, int t, const float* __restrict__ x,
    const float* __restrict__ g1, const float* __restrict__ b1,
    const float* __restrict__ g2, const float* __restrict__ b2,
    float* ss, float* ssq)
{
  float v = x[row*DM + t];
  float s = v, sq = v*v;
  #pragma unroll
  for (int o = 16; o; o >>= 1){
    s  += __shfl_xor_sync(0xffffffffu, s,  o);
    sq += __shfl_xor_sync(0xffffffffu, sq, o);
  }
  int w = t >> 5, ln = t & 31;
  if (ln == 0){ ss[w] = s; ssq[w] = sq; }
  __syncthreads();
  float S = 0.f, SQ = 0.f;
  #pragma unroll
  for (int i = 0; i < 8; i++){ S += ss[i]; SQ += ssq[i]; }
  float mu  = S * (1.0f/DM);
  float var = SQ * (1.0f/DM) - mu*mu;
  float r   = rsqrtf(var + 1e-5f);
  float xn  = (v - mu) * r;
  g_attin[row*DM + t] = __float2half_rn(xn * g1[t] + b1[t]);
  g_ffnin[row*DM + t] = __float2half_rn(xn * g2[t] + b2[t]);
}

// ---- bsum: idx in [0,8192), 256 thr, 8 elems/thread ----
static __device__ void bsum_body(int idx, int tid,
    const float* __restrict__ sp, const float* __restrict__ ed)
{
  const float L2E = 1.4426950408889634f;
  size_t i = ((size_t)idx*256 + tid)*8;
  float4 a0 = *(const float4*)(sp + i), a1 = *(const float4*)(sp + i + 4);
  float4 b0 = *(const float4*)(ed + i), b1 = *(const float4*)(ed + i + 4);
  uint4 o;
  o.x = packh2((a0.y + b0.y)*L2E - BSHIFT, (a0.x + b0.x)*L2E - BSHIFT);
  o.y = packh2((a0.w + b0.w)*L2E - BSHIFT, (a0.z + b0.z)*L2E - BSHIFT);
  o.z = packh2((a1.y + b1.y)*L2E - BSHIFT, (a1.x + b1.x)*L2E - BSHIFT);
  o.w = packh2((a1.w + b1.w)*L2E - BSHIFT, (a1.z + b1.z)*L2E - BSHIFT);
  *(uint4*)(g_bsum + i) = o;
}

// ---- fp16 GEMM body (CTA 128x128, 256 thr, 3-stage cp.async) ----
#define STAGE_BYTES 32768
#define NST 3
#define SMEM_DYN (NST*STAGE_BYTES)

template<int EPI>
static __device__ void gemm_body(int bx, int by, int bz, char* smem,
    const __half* __restrict__ A,
    const __half* __restrict__ Wa, const __half* __restrict__ Wb, const __half* __restrict__ Wc,
    const float* __restrict__ bias, const float* __restrict__ resid,
    const int* __restrict__ flag, int* flagout,
    float* Ca, float* Cb, float* Cc,
    __half* Ha, __half* Hb, __half* Hc, int Nc, int K)
{
  const __half* W = (bz == 0) ? Wa : (bz == 1) ? Wb : Wc;
  float*        C = (bz == 0) ? Ca : (bz == 1) ? Cb : Cc;
  __half*       H = (bz == 0) ? Ha : (bz == 1) ? Hb : Hc;

  const int tid = threadIdx.x, wid = tid >> 5, lane = tid & 31;
  const int wm = wid & 3, wn = wid >> 2;
  const int n0 = bx * 128, m0 = by * 128;
  const uint32_t sb = smem_u32(smem);

  uint32_t dsw[4];
  size_t   srcA[4], srcW[4];
  #pragma unroll
  for (int j = 0; j < 4; j++){
    int seg = tid + j*256;
    int row = seg >> 3, s8 = seg & 7;
    uint32_t d = (uint32_t)(row*128 + s8*16);
    dsw[j]  = d ^ ((d >> 3) & 0x70);
    srcA[j] = (size_t)(m0 + row)*K + s8*8;
    srcW[j] = (size_t)(n0 + row)*K + s8*8;
  }

  float acc[2][8][4];
  #pragma unroll
  for (int mi = 0; mi < 2; mi++)
    #pragma unroll
    for (int nf = 0; nf < 8; nf++)
      #pragma unroll
      for (int q = 0; q < 4; q++) acc[mi][nf][q] = 0.f;

  const int l15 = lane & 15;
  const int kh16 = ((lane >> 4) & 1) * 16;
  const int swx = (l15 & 7) * 16;
  int arow[2], brow[4];
  #pragma unroll
  for (int mi = 0; mi < 2; mi++) arow[mi] = (wm*32 + mi*16 + l15) * 128;
  #pragma unroll
  for (int nj = 0; nj < 4; nj++) brow[nj] = (wn*64 + nj*16 + l15) * 128;

  const int NCh = K >> 6;

  #pragma unroll
  for (int pc = 0; pc < 2; pc++){
    const uint32_t bufb = sb + pc*STAGE_BYTES;
    const int kc = pc << 6;
    #pragma unroll
    for (int j = 0; j < 4; j++){
      CPA16(bufb + dsw[j],          A + srcA[j] + kc);
      CPA16(bufb + 16384 + dsw[j],  W + srcW[j] + kc);
    }
    CPA_COMMIT();
  }

  int bufi = 0;
  for (int i = 0; i < NCh; i++){
    CPA_WAIT(1);
    __syncthreads();
    const uint32_t ahb = sb + bufi*STAGE_BYTES;
    const uint32_t bhb = ahb + 16384;

    #pragma unroll
    for (int ks = 0; ks < 4; ks++){
      const int bc = ks*32 + kh16;
      uint32_t af[2][4], bf_[8][2];
      #pragma unroll
      for (int mi = 0; mi < 2; mi++){
        uint32_t off = arow[mi] + (bc ^ swx);
        LDSM4(af[mi][0], af[mi][1], af[mi][2], af[mi][3], ahb + off);
      }
      #pragma unroll
      for (int nj = 0; nj < 4; nj++){
        uint32_t off = brow[nj] + (bc ^ swx);
        uint32_t t0, t1, t2, t3;
        LDSM4(t0, t1, t2, t3, bhb + off);
        bf_[2*nj][0] = t0;   bf_[2*nj][1] = t2;
        bf_[2*nj+1][0] = t1; bf_[2*nj+1][1] = t3;
      }
      #pragma unroll
      for (int mi = 0; mi < 2; mi++)
        #pragma unroll
        for (int nf = 0; nf < 8; nf++)
          MMAF16(acc[mi][nf], af[mi], bf_[nf]);
    }

    if (i + 2 < NCh){
      const uint32_t bufb = sb + ((i + 2) % NST)*STAGE_BYTES;
      const int kc = (i + 2) << 6;
      #pragma unroll
      for (int j = 0; j < 4; j++){
        CPA16(bufb + dsw[j],          A + srcA[j] + kc);
        CPA16(bufb + 16384 + dsw[j],  W + srcW[j] + kc);
      }
    }
    CPA_COMMIT();
    bufi = (bufi + 1 == NST) ? 0 : bufi + 1;
  }

  const int trow = lane >> 2, tcol = (lane & 3) * 2;
  const float qmul = (EPI == 4 && bz == 0) ? QSCALE : 1.0f;
  #pragma unroll
  for (int mi = 0; mi < 2; mi++){
    #pragma unroll
    for (int half = 0; half < 2; half++){
      const int rg = m0 + wm*32 + mi*16 + trow + half*8;
      int fz = 0;
      if (EPI == 3) fz = flag[rg];
      bool z = false;
      #pragma unroll
      for (int nf = 0; nf < 8; nf++){
        const int cg = n0 + wn*64 + nf*8 + tcol;
        float v0 = acc[mi][nf][2*half + 0];
        float v1 = acc[mi][nf][2*half + 1];
        if (EPI == 1){
          v0 += resid[(size_t)rg*Nc + cg];
          v1 += resid[(size_t)rg*Nc + cg + 1];
          z |= (v0 == 0.f) | (v1 == 0.f);
          *(float2*)&C[(size_t)rg*Nc + cg] = make_float2(v0, v1);
        } else if (EPI == 2){
          v0 = gelu_t(v0 + bias[cg]);
          v1 = gelu_t(v1 + bias[cg + 1]);
          *(uint32_t*)&H[(size_t)rg*Nc + cg] = packh2(v1, v0);
        } else if (EPI == 3){
          v0 = fz ? 0.f : (v0 + bias[cg]     + resid[(size_t)rg*Nc + cg]);
          v1 = fz ? 0.f : (v1 + bias[cg + 1] + resid[(size_t)rg*Nc + cg + 1]);
          *(float2*)&C[(size_t)rg*Nc + cg] = make_float2(v0, v1);
        } else if (EPI == 4){
          *(uint32_t*)&H[(size_t)rg*Nc + cg] = packh2(v1*qmul, v0*qmul);
        }
      }
      if (EPI == 1){
        unsigned bal = __ballot_sync(0xffffffffu, z);
        if (((bal >> (trow*4)) & 0xFu) && (lane & 3) == 0)
          atomicOr(&flagout[rg], 1);
      }
    }
  }
}

// ---- flash attention body (head-split; 256 thr) ----
#define ATT_STG   26624
#define ATT_NST   4
#define ATT_SMEM  (ATT_NST*ATT_STG)

static __device__ __forceinline__ void attn_load(uint32_t stg, int b, int n0, int hh2,
    int kb, int tid,
    const __half* __restrict__ kh, const __half* __restrict__ vh,
    const __half* __restrict__ bsum)
{
  #pragma unroll
  for (int u = 0; u < 2; u++){
    int id = tid*2 + u;
    int row = id >> 4, seg = id & 15;
    const __half* ks = kh + (size_t)(b*SEQ + kb + row)*DM + hh2*128 + seg*8;
    const __half* vs = vh + (size_t)(b*SEQ + kb + row)*DM + hh2*128 + seg*8;
    CPA16(stg + row*272 + seg*16, ks);
    CPA16(stg + 8704 + row*272 + seg*16, vs);
  }
  {
    int row = tid >> 2, seg = tid & 3;
    const __half* s1 = bsum + (size_t)(b*SEQ + n0 + row)*SEQ + kb + seg*8;
    CPA16(stg + 17408 + row*144 + seg*16, s1);
  }
  CPA_COMMIT();
}

static __device__ void attn_body(int qt, int b, int hh2, char* asmem,
    const __half* __restrict__ bsum, const __half* __restrict__ qh,
    const __half* __restrict__ kh, const __half* __restrict__ vh,
    __half* __restrict__ ooh)
{
  const int n0  = qt * 64;
  const int tid = threadIdx.x, wid = tid >> 5, lane = tid & 31;
  const int h4 = wid >> 1, qs = wid & 1;
  const int head = hh2*4 + h4;
  const int l4 = lane >> 2, l2 = (lane & 3) * 2;
  const int l15 = lane & 15, kh16 = ((lane >> 4) & 1) * 16;
  const uint32_t sb = smem_u32(asmem);

  const uint32_t boff = (uint32_t)((qs*32 + (lane & 7) + ((lane >> 3) & 1)*8)*144
                                   + (lane >> 4)*16);

  uint32_t qa[2][2][4];
  {
    const int rbase = b*SEQ + n0 + qs*32;
    #pragma unroll
    for (int mi = 0; mi < 2; mi++)
      #pragma unroll
      for (int ki = 0; ki < 2; ki++){
        int rg = rbase + mi*16 + l4;
        int cg = head*HDIM + ki*16 + l2;
        qa[mi][ki][0] = *(const uint32_t*)&qh[(size_t)rg*DM + cg];
        qa[mi][ki][1] = *(const uint32_t*)&qh[(size_t)(rg+8)*DM + cg];
        qa[mi][ki][2] = *(const uint32_t*)&qh[(size_t)rg*DM + cg + 8];
        qa[mi][ki][3] = *(const uint32_t*)&qh[(size_t)(rg+8)*DM + cg + 8];
      }
  }

  float o[2][4][4];
  #pragma unroll
  for (int mi = 0; mi < 2; mi++)
    #pragma unroll
    for (int nf = 0; nf < 4; nf++)
      #pragma unroll
      for (int q = 0; q < 4; q++) o[mi][nf][q] = 0.f;
  float l_[2][2];
  #pragma unroll
  for (int mi = 0; mi < 2; mi++)
    #pragma unroll
    for (int hf = 0; hf < 2; hf++) l_[mi][hf] = 0.f;

  attn_load(sb,             b, n0, hh2, 0,  tid, kh, vh, bsum);
  attn_load(sb +   ATT_STG, b, n0, hh2, 32, tid, kh, vh, bsum);
  attn_load(sb + 2*ATT_STG, b, n0, hh2, 64, tid, kh, vh, bsum);

  for (int t = 0; t < 32; t++){
    CPA_WAIT(2);
    __syncthreads();
    if (t + 3 < 32){
      attn_load(sb + ((t+3)&3)*ATT_STG, b, n0, hh2, (t+3)*32, tid, kh, vh, bsum);
    } else {
      CPA_COMMIT();
    }

    const uint32_t stg = sb + (t & 3)*ATT_STG;

    uint32_t s[2][4][2];
    #pragma unroll
    for (int mi = 0; mi < 2; mi++)
      #pragma unroll
      for (int nf = 0; nf < 4; nf++){ s[mi][nf][0] = 0u; s[mi][nf][1] = 0u; }

    uint32_t bq[4][2][2];
    #pragma unroll
    for (int njj = 0; njj < 2; njj++)
      #pragma unroll
      for (int ki = 0; ki < 2; ki++){
        uint32_t t0, t1, t2, t3;
        uint32_t addr = stg + (uint32_t)((njj*16 + l15)*272 + h4*64 + ki*32 + kh16);
        LDSM4(t0, t1, t2, t3, addr);
        bq[2*njj][ki][0] = t0;   bq[2*njj][ki][1] = t2;
        bq[2*njj+1][ki][0] = t1; bq[2*njj+1][ki][1] = t3;
      }
    #pragma unroll
    for (int mi = 0; mi < 2; mi++)
      #pragma unroll
      for (int nf = 0; nf < 4; nf++)
        #pragma unroll
        for (int ki = 0; ki < 2; ki++)
          MMAF16H(s[mi][nf], qa[mi][ki], bq[nf][ki]);

    uint32_t bb[2][4][2];
    #pragma unroll
    for (int mi = 0; mi < 2; mi++)
      #pragma unroll
      for (int g = 0; g < 2; g++){
        uint32_t t0, t1, t2, t3;
        uint32_t addr = stg + 17408u + boff + (uint32_t)(mi*2304 + g*32);
        LDSM4(t0, t1, t2, t3, addr);
        bb[mi][2*g][0]   = t0; bb[mi][2*g][1]   = t1;
        bb[mi][2*g+1][0] = t2; bb[mi][2*g+1][1] = t3;
      }

    uint32_t vb[2][4][2];
    #pragma unroll
    for (int kb = 0; kb < 2; kb++)
      #pragma unroll
      for (int dp = 0; dp < 2; dp++){
        uint32_t t0, t1, t2, t3;
        uint32_t addr = stg + 8704u + (uint32_t)((kb*16 + l15)*272 + h4*64 + dp*32 + kh16);
        LDSM4T(t0, t1, t2, t3, addr);
        vb[kb][2*dp][0] = t0;   vb[kb][2*dp][1] = t1;
        vb[kb][2*dp+1][0] = t2; vb[kb][2*dp+1][1] = t3;
      }

    uint32_t ph[2][4][2];
    #pragma unroll
    for (int mi = 0; mi < 2; mi++){
      #pragma unroll
      for (int nf = 0; nf < 4; nf++){
        #pragma unroll
        for (int hf = 0; hf < 2; hf++)
          ph[mi][nf][hf] = ex2h2(hadd2u(s[mi][nf][hf], bb[mi][nf][hf]));
      }
      #pragma unroll
      for (int hf = 0; hf < 2; hf++){
        uint32_t t01 = hadd2u(ph[mi][0][hf], ph[mi][1][hf]);
        uint32_t t23 = hadd2u(ph[mi][2][hf], ph[mi][3][hf]);
        uint32_t tt  = hadd2u(t01, t23);
        float2 tf = __half22float2(*(__half2*)&tt);
        l_[mi][hf] += tf.x + tf.y;
      }
    }

    #pragma unroll
    for (int mi = 0; mi < 2; mi++){
      #pragma unroll
      for (int kb = 0; kb < 2; kb++){
        uint32_t pa[4];
        pa[0] = ph[mi][2*kb][0];
        pa[1] = ph[mi][2*kb][1];
        pa[2] = ph[mi][2*kb+1][0];
        pa[3] = ph[mi][2*kb+1][1];
        #pragma unroll
        for (int nf = 0; nf < 4; nf++)
          MMAF16(o[mi][nf], pa, vb[kb][nf]);
      }
    }
  }

  #pragma unroll
  for (int mi = 0; mi < 2; mi++){
    #pragma unroll
    for (int hf = 0; hf < 2; hf++){
      float lv = l_[mi][hf];
      lv += __shfl_xor_sync(0xffffffffu, lv, 1);
      lv += __shfl_xor_sync(0xffffffffu, lv, 2);
      float inv = (lv > 0.f) ? (1.0f / lv) : 0.0f;
      const int rg = b*SEQ + n0 + qs*32 + mi*16 + hf*8 + l4;
      #pragma unroll
      for (int nf = 0; nf < 4; nf++){
        float v0 = o[mi][nf][2*hf]*inv;
        float v1 = o[mi][nf][2*hf+1]*inv;
        *(uint32_t*)&ooh[(size_t)rg*DM + head*HDIM + nf*8 + l2] = packh2(v1, v0);
      }
    }
  }
}

// ================== fused kernels ===========================================

// prep: wconv (768) + LN (16384) = 17152 blocks
__global__ void __launch_bounds__(256)
prep_kernel(const float* x,
            const float* g1, const float* b1, const float* g2, const float* b2,
            const float* Wq, const float* Wk, const float* Wv,
            const float* Wo, const float* W1, const float* W2)
{
  __shared__ float ss[8], ssq[8];
  if (blockIdx.x < 768)
    wconv_body(blockIdx.x, threadIdx.x, Wq, Wk, Wv, Wo, W1, W2);
  else
    ln_body(blockIdx.x - 768, threadIdx.x, x, g1, b1, g2, b2, ss, ssq);
}

// qkv+bsum: 8960 blocks, mod-35 interleave (3 gemm : 32 bsum per group)
__global__ void __launch_bounds__(256, 2)
qkv_bsum_kernel(const __half* attin, const float* sp, const float* ed,
                __half* qh, __half* kh, __half* vh)
{
  extern __shared__ __align__(128) char smem[];
  const int g = blockIdx.x, q = g / 35, r = g % 35;
  if (r < 3){
    const int gi = q*3 + r;                 // [0,768)
    const int bz = gi >> 8, rem = gi & 255;
    gemm_body<4>(rem & 1, rem >> 1, bz, smem,
                 attin, g_wq, g_wk, g_wv,
                 nullptr, nullptr, nullptr, nullptr,
                 nullptr, nullptr, nullptr,
                 qh, kh, vh, DM, DM);
  } else {
    bsum_body(q*32 + (r - 3), threadIdx.x, sp, ed);
  }
}

// attn+ffn1: 1536 blocks, mod-3 interleave (1 attn : 2 gemm)
__global__ void __launch_bounds__(256, 2)
attn_ffn1_kernel(const __half* bsum, const __half* qh, const __half* kh,
                 const __half* vh, __half* oh,
                 const __half* ffnin, const float* b1, __half* hh)
{
  extern __shared__ __align__(128) char smem[];
  const int g = blockIdx.x, q = g / 3, r = g % 3;
  if (r == 0){
    // q in [0,512): qt = q&15, b = (q>>4)&15, hh2 = q>>8
    attn_body(q & 15, (q >> 4) & 15, q >> 8, smem, bsum, qh, kh, vh, oh);
  } else {
    const int gi = q*2 + (r - 1);           // [0,1024); grid was (8,128)
    gemm_body<2>(gi & 7, gi >> 3, 0, smem,
                 ffnin, g_w1, g_w1, g_w1,
                 b1, nullptr, nullptr, nullptr,
                 nullptr, nullptr, nullptr,
                 hh, hh, hh, FF, DM);
  }
}

// standalone GEMM wrapper (Wo and FFN2)
template<int EPI>
__global__ void __launch_bounds__(256, 2)
gemm_fp16(const __half* A,
          const __half* Wa, const __half* Wb, const __half* Wc,
          const float* bias, const float* resid,
          const int* flag, int* flagout,
          float* Ca, float* Cb, float* Cc,
          __half* Ha, __half* Hb, __half* Hc, int Nc, int K)
{
  extern __shared__ __align__(128) char smem[];
  gemm_body<EPI>(blockIdx.x, blockIdx.y, blockIdx.z, smem,
                 A, Wa, Wb, Wc, bias, resid, flag, flagout,
                 Ca, Cb, Cc, Ha, Hb, Hc, Nc, K);
}

// ---------------- launcher --------------------------------------------------
extern "C" void kernel_launch(void* const* d_in, const int* in_sizes, int n_in,
                              void* d_out, int out_size)
{
  const float* x      = (const float*)d_in[0];
  const float* sp     = (const float*)d_in[1];
  const float* ed     = (const float*)d_in[2];
  const float* gamma1 = (const float*)d_in[3];
  const float* beta1  = (const float*)d_in[4];
  const float* gamma2 = (const float*)d_in[5];
  const float* beta2  = (const float*)d_in[6];
  const float* Wq     = (const float*)d_in[7];
  const float* Wk     = (const float*)d_in[8];
  const float* Wv     = (const float*)d_in[9];
  const float* Wo     = (const float*)d_in[10];
  const float* W1     = (const float*)d_in[11];
  const float* b1     = (const float*)d_in[12];
  const float* W2     = (const float*)d_in[13];
  const float* b2     = (const float*)d_in[14];
  float* out = (float*)d_out;

  __half *attin, *ffnin, *qh, *kh, *vh, *oh, *hh, *bsum;
  float *attnout;
  int* rowflag;
  cudaGetSymbolAddress((void**)&attin,   g_attin);
  cudaGetSymbolAddress((void**)&ffnin,   g_ffnin);
  cudaGetSymbolAddress((void**)&qh,      g_qh);
  cudaGetSymbolAddress((void**)&kh,      g_kh);
  cudaGetSymbolAddress((void**)&vh,      g_vh);
  cudaGetSymbolAddress((void**)&oh,      g_oh);
  cudaGetSymbolAddress((void**)&attnout, g_attnout);
  cudaGetSymbolAddress((void**)&hh,      g_hh);
  cudaGetSymbolAddress((void**)&rowflag, g_rowflag);
  cudaGetSymbolAddress((void**)&bsum,    g_bsum);
  __half *wo2, *w22;
  cudaGetSymbolAddress((void**)&wo2, g_wo);
  cudaGetSymbolAddress((void**)&w22, g_w2);

  cudaFuncSetAttribute(qkv_bsum_kernel,  cudaFuncAttributeMaxDynamicSharedMemorySize, SMEM_DYN);
  cudaFuncSetAttribute(attn_ffn1_kernel, cudaFuncAttributeMaxDynamicSharedMemorySize, ATT_SMEM);
  cudaFuncSetAttribute(gemm_fp16<1>, cudaFuncAttributeMaxDynamicSharedMemorySize, SMEM_DYN);
  cudaFuncSetAttribute(gemm_fp16<3>, cudaFuncAttributeMaxDynamicSharedMemorySize, SMEM_DYN);

  // 1. weights->fp16 + rowflag zero + both LayerNorms (fused)
  prep_kernel<<<17152, 256>>>(x, gamma1, beta1, gamma2, beta2,
                              Wq, Wk, Wv, Wo, W1, W2);

  // 2. QKV projections (tensor) + bias pre-sum (DRAM) co-scheduled
  qkv_bsum_kernel<<<8960, 256, SMEM_DYN>>>(attin, sp, ed, qh, kh, vh);

  // 3. flash attention (latency) + FFN1 gelu (tensor) co-scheduled
  attn_ffn1_kernel<<<1536, 256, ATT_SMEM>>>(bsum, qh, kh, vh, oh,
                                            ffnin, b1, hh);

  // 4. output projection + residual x -> attnout (f32) + rowflag
  gemm_fp16<1><<<dim3(2, 128, 1), 256, SMEM_DYN>>>(oh, wo2, wo2, wo2,
                                                   nullptr, x, nullptr, rowflag,
                                                   attnout, attnout, attnout,
                                                   nullptr, nullptr, nullptr, DM, DM);

  // 5. FFN down + b2 + att_output residual + row masking -> final output
  gemm_fp16<3><<<dim3(2, 128, 1), 256, SMEM_DYN>>>(hh, w22, w22, w22,
                                                   b2, attnout, rowflag, nullptr,
                                                   out, out, out,
                                                   nullptr, nullptr, nullptr, DM, FF);
}

// round 16
// speedup vs baseline: 1.0614x; 1.0614x over previous
#include <cuda_runtime.h>
#include <cuda_fp16.h>
#include <math.h>
#include <stdint.h>

#define BATCH 16
#define SEQ   1024
#define DM    256
#define FF    1024
#define NH    8
#define HDIM  32
#define ROWS  (BATCH*SEQ)   // 16384

#define QSCALE 0.09016844005555556f   // D^-0.5 * log2e
#define BSHIFT 5.770780163555852f     // 4*log2e

// ---------------- scratch (device globals; no cudaMalloc allowed) ----------
__device__ __half g_attin[ROWS*DM];
__device__ __half g_ffnin[ROWS*DM];
__device__ __half g_qh[ROWS*DM], g_kh[ROWS*DM], g_vh[ROWS*DM];
__device__ __half g_oh[ROWS*DM];
__device__ float  g_attnout[ROWS*DM];
__device__ __half g_hh[ROWS*FF];
__device__ int    g_rowflag[ROWS];
__device__ __half g_bsum[(size_t)BATCH*SEQ*SEQ];   // (half)((sp+ed)*log2e - 4*log2e)
__device__ __half g_wq[DM*DM], g_wk[DM*DM], g_wv[DM*DM], g_wo[DM*DM];
__device__ __half g_w1[FF*DM], g_w2[DM*FF];

static __device__ __forceinline__ uint32_t smem_u32(const void* p){
  uint32_t a;
  asm("{ .reg .u64 t; cvta.to.shared.u64 t, %1; cvt.u32.u64 %0, t; }" : "=r"(a) : "l"(p));
  return a;
}

// ---------------- mma.sync / ldmatrix / cp.async ---------------------------
#define LDSM4(r0,r1,r2,r3,addr) \
  asm volatile("ldmatrix.sync.aligned.m8n8.x4.shared.b16 {%0,%1,%2,%3}, [%4];" \
    : "=r"(r0), "=r"(r1), "=r"(r2), "=r"(r3) : "r"(addr))

#define LDSM4T(r0,r1,r2,r3,addr) \
  asm volatile("ldmatrix.sync.aligned.m8n8.x4.trans.shared.b16 {%0,%1,%2,%3}, [%4];" \
    : "=r"(r0), "=r"(r1), "=r"(r2), "=r"(r3) : "r"(addr))

#define MMAF16(c, a, b) \
  asm volatile("mma.sync.aligned.m16n8k16.row.col.f32.f16.f16.f32 " \
    "{%0,%1,%2,%3},{%4,%5,%6,%7},{%8,%9},{%0,%1,%2,%3};" \
    : "+f"((c)[0]), "+f"((c)[1]), "+f"((c)[2]), "+f"((c)[3]) \
    : "r"((a)[0]), "r"((a)[1]), "r"((a)[2]), "r"((a)[3]), \
      "r"((b)[0]), "r"((b)[1]))

#define MMAF16H(c, a, b) \
  asm volatile("mma.sync.aligned.m16n8k16.row.col.f16.f16.f16.f16 " \
    "{%0,%1},{%2,%3,%4,%5},{%6,%7},{%0,%1};" \
    : "+r"((c)[0]), "+r"((c)[1]) \
    : "r"((a)[0]), "r"((a)[1]), "r"((a)[2]), "r"((a)[3]), \
      "r"((b)[0]), "r"((b)[1]))

#define CPA16(dst, src) \
  asm volatile("cp.async.cg.shared.global [%0], [%1], 16;" :: "r"(dst), "l"(src) : "memory")
#define CPA_COMMIT() asm volatile("cp.async.commit_group;" ::: "memory")
#define CPA_WAIT(n)  asm volatile("cp.async.wait_group %0;" :: "n"(n) : "memory")

static __device__ __forceinline__ uint32_t packh2(float hi, float lo){
  uint32_t r; asm("cvt.rn.f16x2.f32 %0, %1, %2;" : "=r"(r) : "f"(hi), "f"(lo)); return r;
}
static __device__ __forceinline__ uint32_t ex2h2(uint32_t y){
  uint32_t r; asm("ex2.approx.f16x2 %0, %1;" : "=r"(r) : "r"(y)); return r;
}
static __device__ __forceinline__ uint32_t hadd2u(uint32_t a, uint32_t b){
  __half2 r = __hadd2(*(__half2*)&a, *(__half2*)&b); return *(uint32_t*)&r;
}

static __device__ __forceinline__ float gelu_t(float x){
  float x3 = x*x*x;
  float u = 0.7978845608028654f * (x + 0.044715f*x3);
  return 0.5f * x * (1.0f + tanhf(u));
}

// ================== memory-bound bodies =====================================

static __device__ void wconv_body(int blk, int tid,
    const float* s0, const float* s1, const float* s2,
    const float* s3, const float* s4, const float* s5)
{
  if (blk < 16)
    ((int4*)g_rowflag)[blk*256 + tid] = make_int4(0,0,0,0);
  int i = (blk*256 + tid)*4;
  const float* src; __half* dst; int off;
  if      (i < 65536)  { src = s0; dst = g_wq; off = i; }
  else if (i < 131072) { src = s1; dst = g_wk; off = i - 65536; }
  else if (i < 196608) { src = s2; dst = g_wv; off = i - 131072; }
  else if (i < 262144) { src = s3; dst = g_wo; off = i - 196608; }
  else if (i < 524288) { src = s4; dst = g_w1; off = i - 262144; }
  else                 { src = s5; dst = g_w2; off = i - 524288; }
  float4 v = *(const float4*)(src + off);
  uint2 o;
  o.x = packh2(v.y, v.x);
  o.y = packh2(v.w, v.z);
  *(uint2*)(dst + off) = o;
}

static __device__ void ln_body(int row, int t, const float* __restrict__ x,
    const float* __restrict__ g1, const float* __restrict__ b1,
    const float* __restrict__ g2, const float* __restrict__ b2,
    float* ss, float* ssq)
{
  float v = x[row*DM + t];
  float s = v, sq = v*v;
  #pragma unroll
  for (int o = 16; o; o >>= 1){
    s  += __shfl_xor_sync(0xffffffffu, s,  o);
    sq += __shfl_xor_sync(0xffffffffu, sq, o);
  }
  int w = t >> 5, ln = t & 31;
  if (ln == 0){ ss[w] = s; ssq[w] = sq; }
  __syncthreads();
  float S = 0.f, SQ = 0.f;
  #pragma unroll
  for (int i = 0; i < 8; i++){ S += ss[i]; SQ += ssq[i]; }
  float mu  = S * (1.0f/DM);
  float var = SQ * (1.0f/DM) - mu*mu;
  float r   = rsqrtf(var + 1e-5f);
  float xn  = (v - mu) * r;
  g_attin[row*DM + t] = __float2half_rn(xn * g1[t] + b1[t]);
  g_ffnin[row*DM + t] = __float2half_rn(xn * g2[t] + b2[t]);
}

static __device__ void bsum_body(int idx, int tid,
    const float* __restrict__ sp, const float* __restrict__ ed)
{
  const float L2E = 1.4426950408889634f;
  size_t i = ((size_t)idx*256 + tid)*8;
  float4 a0 = *(const float4*)(sp + i), a1 = *(const float4*)(sp + i + 4);
  float4 b0 = *(const float4*)(ed + i), b1 = *(const float4*)(ed + i + 4);
  uint4 o;
  o.x = packh2((a0.y + b0.y)*L2E - BSHIFT, (a0.x + b0.x)*L2E - BSHIFT);
  o.y = packh2((a0.w + b0.w)*L2E - BSHIFT, (a0.z + b0.z)*L2E - BSHIFT);
  o.z = packh2((a1.y + b1.y)*L2E - BSHIFT, (a1.x + b1.x)*L2E - BSHIFT);
  o.w = packh2((a1.w + b1.w)*L2E - BSHIFT, (a1.z + b1.z)*L2E - BSHIFT);
  *(uint4*)(g_bsum + i) = o;
}

// prep: bsum (8192) + wconv (768) + LN (16384) = 25344 blocks, all DRAM-bound
__global__ void __launch_bounds__(256)
prep_kernel(const float* x, const float* sp, const float* ed,
            const float* g1, const float* b1, const float* g2, const float* b2,
            const float* Wq, const float* Wk, const float* Wv,
            const float* Wo, const float* W1, const float* W2)
{
  __shared__ float ss[8], ssq[8];
  const int bx = blockIdx.x;
  if (bx < 8192)
    bsum_body(bx, threadIdx.x, sp, ed);
  else if (bx < 8960)
    wconv_body(bx - 8192, threadIdx.x, Wq, Wk, Wv, Wo, W1, W2);
  else
    ln_body(bx - 8960, threadIdx.x, x, g1, b1, g2, b2, ss, ssq);
}

// ---------------- fp16 GEMM, cp.async 3-stage pipeline ---------------------
#define STAGE_BYTES 32768
#define NST 3
#define SMEM_DYN (NST*STAGE_BYTES)

template<int EPI>
__global__ void __launch_bounds__(256, 2)
gemm_fp16(const __half* __restrict__ A,
          const __half* __restrict__ Wa, const __half* __restrict__ Wb, const __half* __restrict__ Wc,
          const float* __restrict__ bias, const float* __restrict__ resid,
          const int* __restrict__ flag, int* flagout,
          float* Ca, float* Cb, float* Cc,
          __half* Ha, __half* Hb, __half* Hc, int Nc, int K)
{
  extern __shared__ __align__(128) char smem[];
  const __half* W = (blockIdx.z == 0) ? Wa : (blockIdx.z == 1) ? Wb : Wc;
  float*        C = (blockIdx.z == 0) ? Ca : (blockIdx.z == 1) ? Cb : Cc;
  __half*       H = (blockIdx.z == 0) ? Ha : (blockIdx.z == 1) ? Hb : Hc;

  const int tid = threadIdx.x, wid = tid >> 5, lane = tid & 31;
  const int wm = wid & 3, wn = wid >> 2;
  const int n0 = blockIdx.x * 128, m0 = blockIdx.y * 128;
  const uint32_t sb = smem_u32(smem);

  uint32_t dsw[4];
  size_t   srcA[4], srcW[4];
  #pragma unroll
  for (int j = 0; j < 4; j++){
    int seg = tid + j*256;
    int row = seg >> 3, s8 = seg & 7;
    uint32_t d = (uint32_t)(row*128 + s8*16);
    dsw[j]  = d ^ ((d >> 3) & 0x70);
    srcA[j] = (size_t)(m0 + row)*K + s8*8;
    srcW[j] = (size_t)(n0 + row)*K + s8*8;
  }

  float acc[2][8][4];
  #pragma unroll
  for (int mi = 0; mi < 2; mi++)
    #pragma unroll
    for (int nf = 0; nf < 8; nf++)
      #pragma unroll
      for (int q = 0; q < 4; q++) acc[mi][nf][q] = 0.f;

  const int l15 = lane & 15;
  const int kh16 = ((lane >> 4) & 1) * 16;
  const int swx = (l15 & 7) * 16;
  int arow[2], brow[4];
  #pragma unroll
  for (int mi = 0; mi < 2; mi++) arow[mi] = (wm*32 + mi*16 + l15) * 128;
  #pragma unroll
  for (int nj = 0; nj < 4; nj++) brow[nj] = (wn*64 + nj*16 + l15) * 128;

  const int NCh = K >> 6;

  #pragma unroll
  for (int pc = 0; pc < 2; pc++){
    const uint32_t bufb = sb + pc*STAGE_BYTES;
    const int kc = pc << 6;
    #pragma unroll
    for (int j = 0; j < 4; j++){
      CPA16(bufb + dsw[j],          A + srcA[j] + kc);
      CPA16(bufb + 16384 + dsw[j],  W + srcW[j] + kc);
    }
    CPA_COMMIT();
  }

  int bufi = 0;
  for (int i = 0; i < NCh; i++){
    CPA_WAIT(1);
    __syncthreads();
    const uint32_t ahb = sb + bufi*STAGE_BYTES;
    const uint32_t bhb = ahb + 16384;

    #pragma unroll
    for (int ks = 0; ks < 4; ks++){
      const int bc = ks*32 + kh16;
      uint32_t af[2][4], bf_[8][2];
      #pragma unroll
      for (int mi = 0; mi < 2; mi++){
        uint32_t off = arow[mi] + (bc ^ swx);
        LDSM4(af[mi][0], af[mi][1], af[mi][2], af[mi][3], ahb + off);
      }
      #pragma unroll
      for (int nj = 0; nj < 4; nj++){
        uint32_t off = brow[nj] + (bc ^ swx);
        uint32_t t0, t1, t2, t3;
        LDSM4(t0, t1, t2, t3, bhb + off);
        bf_[2*nj][0] = t0;   bf_[2*nj][1] = t2;
        bf_[2*nj+1][0] = t1; bf_[2*nj+1][1] = t3;
      }
      #pragma unroll
      for (int mi = 0; mi < 2; mi++)
        #pragma unroll
        for (int nf = 0; nf < 8; nf++)
          MMAF16(acc[mi][nf], af[mi], bf_[nf]);
    }

    if (i + 2 < NCh){
      const uint32_t bufb = sb + ((i + 2) % NST)*STAGE_BYTES;
      const int kc = (i + 2) << 6;
      #pragma unroll
      for (int j = 0; j < 4; j++){
        CPA16(bufb + dsw[j],          A + srcA[j] + kc);
        CPA16(bufb + 16384 + dsw[j],  W + srcW[j] + kc);
      }
    }
    CPA_COMMIT();
    bufi = (bufi + 1 == NST) ? 0 : bufi + 1;
  }

  // epilogue
  const int trow = lane >> 2, tcol = (lane & 3) * 2;
  const float qmul = (EPI == 4 && blockIdx.z == 0) ? QSCALE : 1.0f;
  #pragma unroll
  for (int mi = 0; mi < 2; mi++){
    #pragma unroll
    for (int half = 0; half < 2; half++){
      const int rg = m0 + wm*32 + mi*16 + trow + half*8;
      int fz = 0;
      if (EPI == 3) fz = flag[rg];
      bool z = false;
      #pragma unroll
      for (int nf = 0; nf < 8; nf++){
        const int cg = n0 + wn*64 + nf*8 + tcol;
        float v0 = acc[mi][nf][2*half + 0];
        float v1 = acc[mi][nf][2*half + 1];
        if (EPI == 1){
          v0 += resid[(size_t)rg*Nc + cg];
          v1 += resid[(size_t)rg*Nc + cg + 1];
          z |= (v0 == 0.f) | (v1 == 0.f);
          *(float2*)&C[(size_t)rg*Nc + cg] = make_float2(v0, v1);
        } else if (EPI == 2){
          v0 = gelu_t(v0 + bias[cg]);
          v1 = gelu_t(v1 + bias[cg + 1]);
          *(uint32_t*)&H[(size_t)rg*Nc + cg] = packh2(v1, v0);
        } else if (EPI == 3){
          v0 = fz ? 0.f : (v0 + bias[cg]     + resid[(size_t)rg*Nc + cg]);
          v1 = fz ? 0.f : (v1 + bias[cg + 1] + resid[(size_t)rg*Nc + cg + 1]);
          *(float2*)&C[(size_t)rg*Nc + cg] = make_float2(v0, v1);
        } else if (EPI == 4){
          *(uint32_t*)&H[(size_t)rg*Nc + cg] = packh2(v1*qmul, v0*qmul);
        }
      }
      if (EPI == 1){
        unsigned bal = __ballot_sync(0xffffffffu, z);
        if (((bal >> (trow*4)) & 0xFu) && (lane & 3) == 0)
          atomicOr(&flagout[rg], 1);
      }
    }
  }
}

// ---------------- flash attention: head-split, 2 CTAs/SM -------------------
// grid (16 q-tiles, 16 batch, 2 head-halves), 256 threads = 8 warps.
// stage: K[32 x 128h] rows 272B @0 (8704), V @8704 (8704), bias h[64][72] @17408 (9216)
#define ATT_STG   26624
#define ATT_NST   4
#define ATT_SMEM  (ATT_NST*ATT_STG)

static __device__ __forceinline__ void attn_load(uint32_t stg, int b, int n0, int hh2,
    int kb, int tid,
    const __half* __restrict__ kh, const __half* __restrict__ vh,
    const __half* __restrict__ bsum)
{
  #pragma unroll
  for (int u = 0; u < 2; u++){
    int id = tid*2 + u;
    int row = id >> 4, seg = id & 15;
    const __half* ks = kh + (size_t)(b*SEQ + kb + row)*DM + hh2*128 + seg*8;
    const __half* vs = vh + (size_t)(b*SEQ + kb + row)*DM + hh2*128 + seg*8;
    CPA16(stg + row*272 + seg*16, ks);
    CPA16(stg + 8704 + row*272 + seg*16, vs);
  }
  {
    int row = tid >> 2, seg = tid & 3;
    const __half* s1 = bsum + (size_t)(b*SEQ + n0 + row)*SEQ + kb + seg*8;
    CPA16(stg + 17408 + row*144 + seg*16, s1);
  }
  CPA_COMMIT();
}

__global__ void __launch_bounds__(256, 2)
attn_mma(const __half* __restrict__ bsum,
         const __half* __restrict__ qh, const __half* __restrict__ kh,
         const __half* __restrict__ vh, __half* __restrict__ ooh)
{
  extern __shared__ __align__(128) char asmem[];
  const int n0  = blockIdx.x * 64;
  const int b   = blockIdx.y;
  const int hh2 = blockIdx.z;
  const int tid = threadIdx.x, wid = tid >> 5, lane = tid & 31;
  const int h4 = wid >> 1, qs = wid & 1;
  const int head = hh2*4 + h4;
  const int l4 = lane >> 2, l2 = (lane & 3) * 2;
  const int l15 = lane & 15, kh16 = ((lane >> 4) & 1) * 16;
  const uint32_t sb = smem_u32(asmem);

  const uint32_t boff = (uint32_t)((qs*32 + (lane & 7) + ((lane >> 3) & 1)*8)*144
                                   + (lane >> 4)*16);

  uint32_t qa[2][2][4];
  {
    const int rbase = b*SEQ + n0 + qs*32;
    #pragma unroll
    for (int mi = 0; mi < 2; mi++)
      #pragma unroll
      for (int ki = 0; ki < 2; ki++){
        int rg = rbase + mi*16 + l4;
        int cg = head*HDIM + ki*16 + l2;
        qa[mi][ki][0] = *(const uint32_t*)&qh[(size_t)rg*DM + cg];
        qa[mi][ki][1] = *(const uint32_t*)&qh[(size_t)(rg+8)*DM + cg];
        qa[mi][ki][2] = *(const uint32_t*)&qh[(size_t)rg*DM + cg + 8];
        qa[mi][ki][3] = *(const uint32_t*)&qh[(size_t)(rg+8)*DM + cg + 8];
      }
  }

  float o[2][4][4];
  #pragma unroll
  for (int mi = 0; mi < 2; mi++)
    #pragma unroll
    for (int nf = 0; nf < 4; nf++)
      #pragma unroll
      for (int q = 0; q < 4; q++) o[mi][nf][q] = 0.f;
  float l_[2][2];
  #pragma unroll
  for (int mi = 0; mi < 2; mi++)
    #pragma unroll
    for (int hf = 0; hf < 2; hf++) l_[mi][hf] = 0.f;

  attn_load(sb,             b, n0, hh2, 0,  tid, kh, vh, bsum);
  attn_load(sb +   ATT_STG, b, n0, hh2, 32, tid, kh, vh, bsum);
  attn_load(sb + 2*ATT_STG, b, n0, hh2, 64, tid, kh, vh, bsum);

  for (int t = 0; t < 32; t++){
    CPA_WAIT(2);
    __syncthreads();
    if (t + 3 < 32){
      attn_load(sb + ((t+3)&3)*ATT_STG, b, n0, hh2, (t+3)*32, tid, kh, vh, bsum);
    } else {
      CPA_COMMIT();
    }

    const uint32_t stg = sb + (t & 3)*ATT_STG;

    uint32_t s[2][4][2];
    #pragma unroll
    for (int mi = 0; mi < 2; mi++)
      #pragma unroll
      for (int nf = 0; nf < 4; nf++){ s[mi][nf][0] = 0u; s[mi][nf][1] = 0u; }

    uint32_t bq[4][2][2];
    #pragma unroll
    for (int njj = 0; njj < 2; njj++)
      #pragma unroll
      for (int ki = 0; ki < 2; ki++){
        uint32_t t0, t1, t2, t3;
        uint32_t addr = stg + (uint32_t)((njj*16 + l15)*272 + h4*64 + ki*32 + kh16);
        LDSM4(t0, t1, t2, t3, addr);
        bq[2*njj][ki][0] = t0;   bq[2*njj][ki][1] = t2;
        bq[2*njj+1][ki][0] = t1; bq[2*njj+1][ki][1] = t3;
      }
    #pragma unroll
    for (int mi = 0; mi < 2; mi++)
      #pragma unroll
      for (int nf = 0; nf < 4; nf++)
        #pragma unroll
        for (int ki = 0; ki < 2; ki++)
          MMAF16H(s[mi][nf], qa[mi][ki], bq[nf][ki]);

    uint32_t bb[2][4][2];
    #pragma unroll
    for (int mi = 0; mi < 2; mi++)
      #pragma unroll
      for (int g = 0; g < 2; g++){
        uint32_t t0, t1, t2, t3;
        uint32_t addr = stg + 17408u + boff + (uint32_t)(mi*2304 + g*32);
        LDSM4(t0, t1, t2, t3, addr);
        bb[mi][2*g][0]   = t0; bb[mi][2*g][1]   = t1;
        bb[mi][2*g+1][0] = t2; bb[mi][2*g+1][1] = t3;
      }

    uint32_t vb[2][4][2];
    #pragma unroll
    for (int kb = 0; kb < 2; kb++)
      #pragma unroll
      for (int dp = 0; dp < 2; dp++){
        uint32_t t0, t1, t2, t3;
        uint32_t addr = stg + 8704u + (uint32_t)((kb*16 + l15)*272 + h4*64 + dp*32 + kh16);
        LDSM4T(t0, t1, t2, t3, addr);
        vb[kb][2*dp][0] = t0;   vb[kb][2*dp][1] = t1;
        vb[kb][2*dp+1][0] = t2; vb[kb][2*dp+1][1] = t3;
      }

    uint32_t ph[2][4][2];
    #pragma unroll
    for (int mi = 0; mi < 2; mi++){
      #pragma unroll
      for (int nf = 0; nf < 4; nf++){
        #pragma unroll
        for (int hf = 0; hf < 2; hf++)
          ph[mi][nf][hf] = ex2h2(hadd2u(s[mi][nf][hf], bb[mi][nf][hf]));
      }
      #pragma unroll
      for (int hf = 0; hf < 2; hf++){
        uint32_t t01 = hadd2u(ph[mi][0][hf], ph[mi][1][hf]);
        uint32_t t23 = hadd2u(ph[mi][2][hf], ph[mi][3][hf]);
        uint32_t tt  = hadd2u(t01, t23);
        float2 tf = __half22float2(*(__half2*)&tt);
        l_[mi][hf] += tf.x + tf.y;
      }
    }

    #pragma unroll
    for (int mi = 0; mi < 2; mi++){
      #pragma unroll
      for (int kb = 0; kb < 2; kb++){
        uint32_t pa[4];
        pa[0] = ph[mi][2*kb][0];
        pa[1] = ph[mi][2*kb][1];
        pa[2] = ph[mi][2*kb+1][0];
        pa[3] = ph[mi][2*kb+1][1];
        #pragma unroll
        for (int nf = 0; nf < 4; nf++)
          MMAF16(o[mi][nf], pa, vb[kb][nf]);
      }
    }
  }

  #pragma unroll
  for (int mi = 0; mi < 2; mi++){
    #pragma unroll
    for (int hf = 0; hf < 2; hf++){
      float lv = l_[mi][hf];
      lv += __shfl_xor_sync(0xffffffffu, lv, 1);
      lv += __shfl_xor_sync(0xffffffffu, lv, 2);
      float inv = (lv > 0.f) ? (1.0f / lv) : 0.0f;
      const int rg = b*SEQ + n0 + qs*32 + mi*16 + hf*8 + l4;
      #pragma unroll
      for (int nf = 0; nf < 4; nf++){
        float v0 = o[mi][nf][2*hf]*inv;
        float v1 = o[mi][nf][2*hf+1]*inv;
        *(uint32_t*)&ooh[(size_t)rg*DM + head*HDIM + nf*8 + l2] = packh2(v1, v0);
      }
    }
  }
}

// ---------------- launcher --------------------------------------------------
extern "C" void kernel_launch(void* const* d_in, const int* in_sizes, int n_in,
                              void* d_out, int out_size)
{
  const float* x      = (const float*)d_in[0];
  const float* sp     = (const float*)d_in[1];
  const float* ed     = (const float*)d_in[2];
  const float* gamma1 = (const float*)d_in[3];
  const float* beta1  = (const float*)d_in[4];
  const float* gamma2 = (const float*)d_in[5];
  const float* beta2  = (const float*)d_in[6];
  const float* Wq     = (const float*)d_in[7];
  const float* Wk     = (const float*)d_in[8];
  const float* Wv     = (const float*)d_in[9];
  const float* Wo     = (const float*)d_in[10];
  const float* W1     = (const float*)d_in[11];
  const float* b1     = (const float*)d_in[12];
  const float* W2     = (const float*)d_in[13];
  const float* b2     = (const float*)d_in[14];
  float* out = (float*)d_out;

  __half *attin, *ffnin, *qh, *kh, *vh, *oh, *hh, *bsum;
  __half *wq, *wk, *wv, *wo, *w1, *w2;
  float *attnout;
  int* rowflag;
  cudaGetSymbolAddress((void**)&attin,   g_attin);
  cudaGetSymbolAddress((void**)&ffnin,   g_ffnin);
  cudaGetSymbolAddress((void**)&qh,      g_qh);
  cudaGetSymbolAddress((void**)&kh,      g_kh);
  cudaGetSymbolAddress((void**)&vh,      g_vh);
  cudaGetSymbolAddress((void**)&oh,      g_oh);
  cudaGetSymbolAddress((void**)&attnout, g_attnout);
  cudaGetSymbolAddress((void**)&hh,      g_hh);
  cudaGetSymbolAddress((void**)&rowflag, g_rowflag);
  cudaGetSymbolAddress((void**)&bsum,    g_bsum);
  cudaGetSymbolAddress((void**)&wq, g_wq);
  cudaGetSymbolAddress((void**)&wk, g_wk);
  cudaGetSymbolAddress((void**)&wv, g_wv);
  cudaGetSymbolAddress((void**)&wo, g_wo);
  cudaGetSymbolAddress((void**)&w1, g_w1);
  cudaGetSymbolAddress((void**)&w2, g_w2);

  cudaFuncSetAttribute(gemm_fp16<1>, cudaFuncAttributeMaxDynamicSharedMemorySize, SMEM_DYN);
  cudaFuncSetAttribute(gemm_fp16<2>, cudaFuncAttributeMaxDynamicSharedMemorySize, SMEM_DYN);
  cudaFuncSetAttribute(gemm_fp16<3>, cudaFuncAttributeMaxDynamicSharedMemorySize, SMEM_DYN);
  cudaFuncSetAttribute(gemm_fp16<4>, cudaFuncAttributeMaxDynamicSharedMemorySize, SMEM_DYN);
  cudaFuncSetAttribute(attn_mma,     cudaFuncAttributeMaxDynamicSharedMemorySize, ATT_SMEM);

  // 1. prep: bsum + weight conversion + rowflag zero + both LayerNorms
  prep_kernel<<<25344, 256>>>(x, sp, ed, gamma1, beta1, gamma2, beta2,
                              Wq, Wk, Wv, Wo, W1, W2);

  // 2. Q,K,V projections -> fp16 (Q pre-scaled by scale*log2e)
  gemm_fp16<4><<<dim3(2, 128, 3), 256, SMEM_DYN>>>(attin, wq, wk, wv,
                                                   nullptr, nullptr, nullptr, nullptr,
                                                   nullptr, nullptr, nullptr,
                                                   qh, kh, vh, DM, DM);

  // 3. flash attention -> o fp16 (head-split, 2 CTAs/SM)
  attn_mma<<<dim3(SEQ/64, BATCH, 2), 256, ATT_SMEM>>>(bsum, qh, kh, vh, oh);

  // 4. output projection + residual x -> attnout (f32) + rowflag (fused)
  gemm_fp16<1><<<dim3(2, 128, 1), 256, SMEM_DYN>>>(oh, wo, wo, wo,
                                                   nullptr, x, nullptr, rowflag,
                                                   attnout, attnout, attnout,
                                                   nullptr, nullptr, nullptr, DM, DM);

  // 5. FFN up + gelu -> h fp16
  gemm_fp16<2><<<dim3(8, 128, 1), 256, SMEM_DYN>>>(ffnin, w1, w1, w1,
                                                   b1, nullptr, nullptr, nullptr,
                                                   nullptr, nullptr, nullptr,
                                                   hh, hh, hh, FF, DM);

  // 6. FFN down + b2 + att_output residual + row masking -> final output
  gemm_fp16<3><<<dim3(2, 128, 1), 256, SMEM_DYN>>>(hh, w2, w2, w2,
                                                   b2, attnout, rowflag, nullptr,
                                                   out, out, out,
                                                   nullptr, nullptr, nullptr, DM, FF);
}

// round 17
// speedup vs baseline: 1.0781x; 1.0157x over previous
#include <cuda_runtime.h>
#include <cuda_fp16.h>
#include <math.h>
#include <stdint.h>

#define BATCH 16
#define SEQ   1024
#define DM    256
#define FF    1024
#define NH    8
#define HDIM  32
#define ROWS  (BATCH*SEQ)   // 16384

#define QSCALE 0.09016844005555556f   // D^-0.5 * log2e
#define BSHIFT 5.770780163555852f     // 4*log2e

// ---------------- scratch (device globals; no cudaMalloc allowed) ----------
__device__ __half g_attin[ROWS*DM];
__device__ __half g_ffnin[ROWS*DM];
__device__ __half g_qh[ROWS*DM], g_kh[ROWS*DM], g_vh[ROWS*DM];
__device__ __half g_oh[ROWS*DM];
__device__ float  g_attnout[ROWS*DM];
__device__ __half g_hh[ROWS*FF];
__device__ int    g_rowflag[ROWS];
__device__ __half g_bsum[(size_t)BATCH*SEQ*SEQ];   // (half)((sp+ed)*log2e - 4*log2e)
__device__ __half g_wq[DM*DM], g_wk[DM*DM], g_wv[DM*DM], g_wo[DM*DM];
__device__ __half g_w1[FF*DM], g_w2[DM*FF];

static __device__ __forceinline__ uint32_t smem_u32(const void* p){
  uint32_t a;
  asm("{ .reg .u64 t; cvta.to.shared.u64 t, %1; cvt.u32.u64 %0, t; }" : "=r"(a) : "l"(p));
  return a;
}

// ---------------- mma.sync / ldmatrix / cp.async ---------------------------
#define LDSM4(r0,r1,r2,r3,addr) \
  asm volatile("ldmatrix.sync.aligned.m8n8.x4.shared.b16 {%0,%1,%2,%3}, [%4];" \
    : "=r"(r0), "=r"(r1), "=r"(r2), "=r"(r3) : "r"(addr))

#define LDSM4T(r0,r1,r2,r3,addr) \
  asm volatile("ldmatrix.sync.aligned.m8n8.x4.trans.shared.b16 {%0,%1,%2,%3}, [%4];" \
    : "=r"(r0), "=r"(r1), "=r"(r2), "=r"(r3) : "r"(addr))

#define MMAF16(c, a, b) \
  asm volatile("mma.sync.aligned.m16n8k16.row.col.f32.f16.f16.f32 " \
    "{%0,%1,%2,%3},{%4,%5,%6,%7},{%8,%9},{%0,%1,%2,%3};" \
    : "+f"((c)[0]), "+f"((c)[1]), "+f"((c)[2]), "+f"((c)[3]) \
    : "r"((a)[0]), "r"((a)[1]), "r"((a)[2]), "r"((a)[3]), \
      "r"((b)[0]), "r"((b)[1]))

#define MMAF16H(c, a, b) \
  asm volatile("mma.sync.aligned.m16n8k16.row.col.f16.f16.f16.f16 " \
    "{%0,%1},{%2,%3,%4,%5},{%6,%7},{%0,%1};" \
    : "+r"((c)[0]), "+r"((c)[1]) \
    : "r"((a)[0]), "r"((a)[1]), "r"((a)[2]), "r"((a)[3]), \
      "r"((b)[0]), "r"((b)[1]))

#define CPA16(dst, src) \
  asm volatile("cp.async.cg.shared.global [%0], [%1], 16;" :: "r"(dst), "l"(src) : "memory")
#define CPA_COMMIT() asm volatile("cp.async.commit_group;" ::: "memory")
#define CPA_WAIT(n)  asm volatile("cp.async.wait_group %0;" :: "n"(n) : "memory")

static __device__ __forceinline__ uint32_t packh2(float hi, float lo){
  uint32_t r; asm("cvt.rn.f16x2.f32 %0, %1, %2;" : "=r"(r) : "f"(hi), "f"(lo)); return r;
}
static __device__ __forceinline__ uint32_t ex2h2(uint32_t y){
  uint32_t r; asm("ex2.approx.f16x2 %0, %1;" : "=r"(r) : "r"(y)); return r;
}
static __device__ __forceinline__ uint32_t hadd2u(uint32_t a, uint32_t b){
  __half2 r = __hadd2(*(__half2*)&a, *(__half2*)&b); return *(uint32_t*)&r;
}

static __device__ __forceinline__ float gelu_t(float x){
  float x3 = x*x*x;
  float u = 0.7978845608028654f * (x + 0.044715f*x3);
  return 0.5f * x * (1.0f + tanhf(u));
}

// ================== memory-bound bodies =====================================

static __device__ void wconv_body(int blk, int tid,
    const float* s0, const float* s1, const float* s2,
    const float* s3, const float* s4, const float* s5)
{
  if (blk < 16)
    ((int4*)g_rowflag)[blk*256 + tid] = make_int4(0,0,0,0);
  int i = (blk*256 + tid)*4;
  const float* src; __half* dst; int off;
  if      (i < 65536)  { src = s0; dst = g_wq; off = i; }
  else if (i < 131072) { src = s1; dst = g_wk; off = i - 65536; }
  else if (i < 196608) { src = s2; dst = g_wv; off = i - 131072; }
  else if (i < 262144) { src = s3; dst = g_wo; off = i - 196608; }
  else if (i < 524288) { src = s4; dst = g_w1; off = i - 262144; }
  else                 { src = s5; dst = g_w2; off = i - 524288; }
  float4 v = *(const float4*)(src + off);
  uint2 o;
  o.x = packh2(v.y, v.x);
  o.y = packh2(v.w, v.z);
  *(uint2*)(dst + off) = o;
}

static __device__ void ln_body(int row, int t, const float* __restrict__ x,
    const float* __restrict__ g1, const float* __restrict__ b1,
    const float* __restrict__ g2, const float* __restrict__ b2,
    float* ss, float* ssq)
{
  float v = x[row*DM + t];
  float s = v, sq = v*v;
  #pragma unroll
  for (int o = 16; o; o >>= 1){
    s  += __shfl_xor_sync(0xffffffffu, s,  o);
    sq += __shfl_xor_sync(0xffffffffu, sq, o);
  }
  int w = t >> 5, ln = t & 31;
  if (ln == 0){ ss[w] = s; ssq[w] = sq; }
  __syncthreads();
  float S = 0.f, SQ = 0.f;
  #pragma unroll
  for (int i = 0; i < 8; i++){ S += ss[i]; SQ += ssq[i]; }
  float mu  = S * (1.0f/DM);
  float var = SQ * (1.0f/DM) - mu*mu;
  float r   = rsqrtf(var + 1e-5f);
  float xn  = (v - mu) * r;
  g_attin[row*DM + t] = __float2half_rn(xn * g1[t] + b1[t]);
  g_ffnin[row*DM + t] = __float2half_rn(xn * g2[t] + b2[t]);
}

static __device__ void bsum_body(int idx, int tid,
    const float* __restrict__ sp, const float* __restrict__ ed)
{
  const float L2E = 1.4426950408889634f;
  size_t i = ((size_t)idx*256 + tid)*8;
  float4 a0 = *(const float4*)(sp + i), a1 = *(const float4*)(sp + i + 4);
  float4 b0 = *(const float4*)(ed + i), b1 = *(const float4*)(ed + i + 4);
  uint4 o;
  o.x = packh2((a0.y + b0.y)*L2E - BSHIFT, (a0.x + b0.x)*L2E - BSHIFT);
  o.y = packh2((a0.w + b0.w)*L2E - BSHIFT, (a0.z + b0.z)*L2E - BSHIFT);
  o.z = packh2((a1.y + b1.y)*L2E - BSHIFT, (a1.x + b1.x)*L2E - BSHIFT);
  o.w = packh2((a1.w + b1.w)*L2E - BSHIFT, (a1.z + b1.z)*L2E - BSHIFT);
  *(uint4*)(g_bsum + i) = o;
}

// prep: bsum (8192) + wconv (768) + LN (16384) = 25344 blocks, all DRAM-bound
__global__ void __launch_bounds__(256)
prep_kernel(const float* x, const float* sp, const float* ed,
            const float* g1, const float* b1, const float* g2, const float* b2,
            const float* Wq, const float* Wk, const float* Wv,
            const float* Wo, const float* W1, const float* W2)
{
  __shared__ float ss[8], ssq[8];
  const int bx = blockIdx.x;
  if (bx < 8192)
    bsum_body(bx, threadIdx.x, sp, ed);
  else if (bx < 8960)
    wconv_body(bx - 8192, threadIdx.x, Wq, Wk, Wv, Wo, W1, W2);
  else
    ln_body(bx - 8960, threadIdx.x, x, g1, b1, g2, b2, ss, ssq);
}

// ---------------- fp16 GEMM body (CTA 128x128, 256 thr, 3-stage cp.async) --
#define STAGE_BYTES 32768
#define NST 3
#define SMEM_DYN (NST*STAGE_BYTES)

template<int EPI>
static __device__ void gemm_body(int bx, int by, int bz, char* smem,
    const __half* __restrict__ A,
    const __half* __restrict__ Wa, const __half* __restrict__ Wb, const __half* __restrict__ Wc,
    const float* __restrict__ bias, const float* __restrict__ resid,
    const int* __restrict__ flag, int* flagout,
    float* Ca, float* Cb, float* Cc,
    __half* Ha, __half* Hb, __half* Hc, int Nc, int K)
{
  const __half* W = (bz == 0) ? Wa : (bz == 1) ? Wb : Wc;
  float*        C = (bz == 0) ? Ca : (bz == 1) ? Cb : Cc;
  __half*       H = (bz == 0) ? Ha : (bz == 1) ? Hb : Hc;

  const int tid = threadIdx.x, wid = tid >> 5, lane = tid & 31;
  const int wm = wid & 3, wn = wid >> 2;
  const int n0 = bx * 128, m0 = by * 128;
  const uint32_t sb = smem_u32(smem);

  uint32_t dsw[4];
  size_t   srcA[4], srcW[4];
  #pragma unroll
  for (int j = 0; j < 4; j++){
    int seg = tid + j*256;
    int row = seg >> 3, s8 = seg & 7;
    uint32_t d = (uint32_t)(row*128 + s8*16);
    dsw[j]  = d ^ ((d >> 3) & 0x70);
    srcA[j] = (size_t)(m0 + row)*K + s8*8;
    srcW[j] = (size_t)(n0 + row)*K + s8*8;
  }

  float acc[2][8][4];
  #pragma unroll
  for (int mi = 0; mi < 2; mi++)
    #pragma unroll
    for (int nf = 0; nf < 8; nf++)
      #pragma unroll
      for (int q = 0; q < 4; q++) acc[mi][nf][q] = 0.f;

  const int l15 = lane & 15;
  const int kh16 = ((lane >> 4) & 1) * 16;
  const int swx = (l15 & 7) * 16;
  int arow[2], brow[4];
  #pragma unroll
  for (int mi = 0; mi < 2; mi++) arow[mi] = (wm*32 + mi*16 + l15) * 128;
  #pragma unroll
  for (int nj = 0; nj < 4; nj++) brow[nj] = (wn*64 + nj*16 + l15) * 128;

  const int NCh = K >> 6;

  #pragma unroll
  for (int pc = 0; pc < 2; pc++){
    const uint32_t bufb = sb + pc*STAGE_BYTES;
    const int kc = pc << 6;
    #pragma unroll
    for (int j = 0; j < 4; j++){
      CPA16(bufb + dsw[j],          A + srcA[j] + kc);
      CPA16(bufb + 16384 + dsw[j],  W + srcW[j] + kc);
    }
    CPA_COMMIT();
  }

  int bufi = 0;
  for (int i = 0; i < NCh; i++){
    CPA_WAIT(1);
    __syncthreads();
    const uint32_t ahb = sb + bufi*STAGE_BYTES;
    const uint32_t bhb = ahb + 16384;

    #pragma unroll
    for (int ks = 0; ks < 4; ks++){
      const int bc = ks*32 + kh16;
      uint32_t af[2][4], bf_[8][2];
      #pragma unroll
      for (int mi = 0; mi < 2; mi++){
        uint32_t off = arow[mi] + (bc ^ swx);
        LDSM4(af[mi][0], af[mi][1], af[mi][2], af[mi][3], ahb + off);
      }
      #pragma unroll
      for (int nj = 0; nj < 4; nj++){
        uint32_t off = brow[nj] + (bc ^ swx);
        uint32_t t0, t1, t2, t3;
        LDSM4(t0, t1, t2, t3, bhb + off);
        bf_[2*nj][0] = t0;   bf_[2*nj][1] = t2;
        bf_[2*nj+1][0] = t1; bf_[2*nj+1][1] = t3;
      }
      #pragma unroll
      for (int mi = 0; mi < 2; mi++)
        #pragma unroll
        for (int nf = 0; nf < 8; nf++)
          MMAF16(acc[mi][nf], af[mi], bf_[nf]);
    }

    if (i + 2 < NCh){
      const uint32_t bufb = sb + ((i + 2) % NST)*STAGE_BYTES;
      const int kc = (i + 2) << 6;
      #pragma unroll
      for (int j = 0; j < 4; j++){
        CPA16(bufb + dsw[j],          A + srcA[j] + kc);
        CPA16(bufb + 16384 + dsw[j],  W + srcW[j] + kc);
      }
    }
    CPA_COMMIT();
    bufi = (bufi + 1 == NST) ? 0 : bufi + 1;
  }

  const int trow = lane >> 2, tcol = (lane & 3) * 2;
  const float qmul = (EPI == 4 && bz == 0) ? QSCALE : 1.0f;
  #pragma unroll
  for (int mi = 0; mi < 2; mi++){
    #pragma unroll
    for (int half = 0; half < 2; half++){
      const int rg = m0 + wm*32 + mi*16 + trow + half*8;
      int fz = 0;
      if (EPI == 3) fz = flag[rg];
      bool z = false;
      #pragma unroll
      for (int nf = 0; nf < 8; nf++){
        const int cg = n0 + wn*64 + nf*8 + tcol;
        float v0 = acc[mi][nf][2*half + 0];
        float v1 = acc[mi][nf][2*half + 1];
        if (EPI == 1){
          v0 += resid[(size_t)rg*Nc + cg];
          v1 += resid[(size_t)rg*Nc + cg + 1];
          z |= (v0 == 0.f) | (v1 == 0.f);
          *(float2*)&C[(size_t)rg*Nc + cg] = make_float2(v0, v1);
        } else if (EPI == 2){
          v0 = gelu_t(v0 + bias[cg]);
          v1 = gelu_t(v1 + bias[cg + 1]);
          *(uint32_t*)&H[(size_t)rg*Nc + cg] = packh2(v1, v0);
        } else if (EPI == 3){
          v0 = fz ? 0.f : (v0 + bias[cg]     + resid[(size_t)rg*Nc + cg]);
          v1 = fz ? 0.f : (v1 + bias[cg + 1] + resid[(size_t)rg*Nc + cg + 1]);
          *(float2*)&C[(size_t)rg*Nc + cg] = make_float2(v0, v1);
        } else if (EPI == 4){
          *(uint32_t*)&H[(size_t)rg*Nc + cg] = packh2(v1*qmul, v0*qmul);
        }
      }
      if (EPI == 1){
        unsigned bal = __ballot_sync(0xffffffffu, z);
        if (((bal >> (trow*4)) & 0xFu) && (lane & 3) == 0)
          atomicOr(&flagout[rg], 1);
      }
    }
  }
}

// standalone GEMM wrapper (QKV and FFN2)
template<int EPI>
__global__ void __launch_bounds__(256, 2)
gemm_fp16(const __half* A,
          const __half* Wa, const __half* Wb, const __half* Wc,
          const float* bias, const float* resid,
          const int* flag, int* flagout,
          float* Ca, float* Cb, float* Cc,
          __half* Ha, __half* Hb, __half* Hc, int Nc, int K)
{
  extern __shared__ __align__(128) char smem[];
  gemm_body<EPI>(blockIdx.x, blockIdx.y, blockIdx.z, smem,
                 A, Wa, Wb, Wc, bias, resid, flag, flagout,
                 Ca, Cb, Cc, Ha, Hb, Hc, Nc, K);
}

// merged Wo + FFN1: both K=256, identical per-CTA cost (homogeneous fusion).
// blocks [0,256): Wo  (EPI 1, grid 2x128, resid=x, writes attnout+rowflag)
// blocks [256,1280): FFN1 (EPI 2, grid 8x128, bias=b1, writes hh fp16)
__global__ void __launch_bounds__(256, 2)
wo_ffn1_kernel(const __half* oh, const float* x, int* rowflag, float* attnout,
               const __half* ffnin, const float* b1, __half* hh)
{
  extern __shared__ __align__(128) char smem[];
  const int g = blockIdx.x;
  if (g < 256){
    gemm_body<1>(g & 1, g >> 1, 0, smem,
                 oh, g_wo, g_wo, g_wo,
                 nullptr, x, nullptr, rowflag,
                 attnout, attnout, attnout,
                 nullptr, nullptr, nullptr, DM, DM);
  } else {
    const int gi = g - 256;           // [0,1024): grid was (8,128)
    gemm_body<2>(gi & 7, gi >> 3, 0, smem,
                 ffnin, g_w1, g_w1, g_w1,
                 b1, nullptr, nullptr, nullptr,
                 nullptr, nullptr, nullptr,
                 hh, hh, hh, FF, DM);
  }
}

// ---------------- flash attention: head-split, 2 CTAs/SM -------------------
// grid (16 q-tiles, 16 batch, 2 head-halves), 256 threads = 8 warps.
// stage: K[32 x 128h] rows 272B @0 (8704), V @8704 (8704), bias h[64][72] @17408 (9216)
#define ATT_STG   26624
#define ATT_NST   4
#define ATT_SMEM  (ATT_NST*ATT_STG)

static __device__ __forceinline__ void attn_load(uint32_t stg, int b, int n0, int hh2,
    int kb, int tid,
    const __half* __restrict__ kh, const __half* __restrict__ vh,
    const __half* __restrict__ bsum)
{
  #pragma unroll
  for (int u = 0; u < 2; u++){
    int id = tid*2 + u;
    int row = id >> 4, seg = id & 15;
    const __half* ks = kh + (size_t)(b*SEQ + kb + row)*DM + hh2*128 + seg*8;
    const __half* vs = vh + (size_t)(b*SEQ + kb + row)*DM + hh2*128 + seg*8;
    CPA16(stg + row*272 + seg*16, ks);
    CPA16(stg + 8704 + row*272 + seg*16, vs);
  }
  {
    int row = tid >> 2, seg = tid & 3;
    const __half* s1 = bsum + (size_t)(b*SEQ + n0 + row)*SEQ + kb + seg*8;
    CPA16(stg + 17408 + row*144 + seg*16, s1);
  }
  CPA_COMMIT();
}

__global__ void __launch_bounds__(256, 2)
attn_mma(const __half* __restrict__ bsum,
         const __half* __restrict__ qh, const __half* __restrict__ kh,
         const __half* __restrict__ vh, __half* __restrict__ ooh)
{
  extern __shared__ __align__(128) char asmem[];
  const int n0  = blockIdx.x * 64;
  const int b   = blockIdx.y;
  const int hh2 = blockIdx.z;
  const int tid = threadIdx.x, wid = tid >> 5, lane = tid & 31;
  const int h4 = wid >> 1, qs = wid & 1;
  const int head = hh2*4 + h4;
  const int l4 = lane >> 2, l2 = (lane & 3) * 2;
  const int l15 = lane & 15, kh16 = ((lane >> 4) & 1) * 16;
  const uint32_t sb = smem_u32(asmem);

  const uint32_t boff = (uint32_t)((qs*32 + (lane & 7) + ((lane >> 3) & 1)*8)*144
                                   + (lane >> 4)*16);

  uint32_t qa[2][2][4];
  {
    const int rbase = b*SEQ + n0 + qs*32;
    #pragma unroll
    for (int mi = 0; mi < 2; mi++)
      #pragma unroll
      for (int ki = 0; ki < 2; ki++){
        int rg = rbase + mi*16 + l4;
        int cg = head*HDIM + ki*16 + l2;
        qa[mi][ki][0] = *(const uint32_t*)&qh[(size_t)rg*DM + cg];
        qa[mi][ki][1] = *(const uint32_t*)&qh[(size_t)(rg+8)*DM + cg];
        qa[mi][ki][2] = *(const uint32_t*)&qh[(size_t)rg*DM + cg + 8];
        qa[mi][ki][3] = *(const uint32_t*)&qh[(size_t)(rg+8)*DM + cg + 8];
      }
  }

  float o[2][4][4];
  #pragma unroll
  for (int mi = 0; mi < 2; mi++)
    #pragma unroll
    for (int nf = 0; nf < 4; nf++)
      #pragma unroll
      for (int q = 0; q < 4; q++) o[mi][nf][q] = 0.f;
  float l_[2][2];
  #pragma unroll
  for (int mi = 0; mi < 2; mi++)
    #pragma unroll
    for (int hf = 0; hf < 2; hf++) l_[mi][hf] = 0.f;

  attn_load(sb,             b, n0, hh2, 0,  tid, kh, vh, bsum);
  attn_load(sb +   ATT_STG, b, n0, hh2, 32, tid, kh, vh, bsum);
  attn_load(sb + 2*ATT_STG, b, n0, hh2, 64, tid, kh, vh, bsum);

  for (int t = 0; t < 32; t++){
    CPA_WAIT(2);
    __syncthreads();
    if (t + 3 < 32){
      attn_load(sb + ((t+3)&3)*ATT_STG, b, n0, hh2, (t+3)*32, tid, kh, vh, bsum);
    } else {
      CPA_COMMIT();
    }

    const uint32_t stg = sb + (t & 3)*ATT_STG;

    uint32_t s[2][4][2];
    #pragma unroll
    for (int mi = 0; mi < 2; mi++)
      #pragma unroll
      for (int nf = 0; nf < 4; nf++){ s[mi][nf][0] = 0u; s[mi][nf][1] = 0u; }

    uint32_t bq[4][2][2];
    #pragma unroll
    for (int njj = 0; njj < 2; njj++)
      #pragma unroll
      for (int ki = 0; ki < 2; ki++){
        uint32_t t0, t1, t2, t3;
        uint32_t addr = stg + (uint32_t)((njj*16 + l15)*272 + h4*64 + ki*32 + kh16);
        LDSM4(t0, t1, t2, t3, addr);
        bq[2*njj][ki][0] = t0;   bq[2*njj][ki][1] = t2;
        bq[2*njj+1][ki][0] = t1; bq[2*njj+1][ki][1] = t3;
      }
    #pragma unroll
    for (int mi = 0; mi < 2; mi++)
      #pragma unroll
      for (int nf = 0; nf < 4; nf++)
        #pragma unroll
        for (int ki = 0; ki < 2; ki++)
          MMAF16H(s[mi][nf], qa[mi][ki], bq[nf][ki]);

    uint32_t bb[2][4][2];
    #pragma unroll
    for (int mi = 0; mi < 2; mi++)
      #pragma unroll
      for (int g = 0; g < 2; g++){
        uint32_t t0, t1, t2, t3;
        uint32_t addr = stg + 17408u + boff + (uint32_t)(mi*2304 + g*32);
        LDSM4(t0, t1, t2, t3, addr);
        bb[mi][2*g][0]   = t0; bb[mi][2*g][1]   = t1;
        bb[mi][2*g+1][0] = t2; bb[mi][2*g+1][1] = t3;
      }

    uint32_t vb[2][4][2];
    #pragma unroll
    for (int kb = 0; kb < 2; kb++)
      #pragma unroll
      for (int dp = 0; dp < 2; dp++){
        uint32_t t0, t1, t2, t3;
        uint32_t addr = stg + 8704u + (uint32_t)((kb*16 + l15)*272 + h4*64 + dp*32 + kh16);
        LDSM4T(t0, t1, t2, t3, addr);
        vb[kb][2*dp][0] = t0;   vb[kb][2*dp][1] = t1;
        vb[kb][2*dp+1][0] = t2; vb[kb][2*dp+1][1] = t3;
      }

    uint32_t ph[2][4][2];
    #pragma unroll
    for (int mi = 0; mi < 2; mi++){
      #pragma unroll
      for (int nf = 0; nf < 4; nf++){
        #pragma unroll
        for (int hf = 0; hf < 2; hf++)
          ph[mi][nf][hf] = ex2h2(hadd2u(s[mi][nf][hf], bb[mi][nf][hf]));
      }
      #pragma unroll
      for (int hf = 0; hf < 2; hf++){
        uint32_t t01 = hadd2u(ph[mi][0][hf], ph[mi][1][hf]);
        uint32_t t23 = hadd2u(ph[mi][2][hf], ph[mi][3][hf]);
        uint32_t tt  = hadd2u(t01, t23);
        float2 tf = __half22float2(*(__half2*)&tt);
        l_[mi][hf] += tf.x + tf.y;
      }
    }

    #pragma unroll
    for (int mi = 0; mi < 2; mi++){
      #pragma unroll
      for (int kb = 0; kb < 2; kb++){
        uint32_t pa[4];
        pa[0] = ph[mi][2*kb][0];
        pa[1] = ph[mi][2*kb][1];
        pa[2] = ph[mi][2*kb+1][0];
        pa[3] = ph[mi][2*kb+1][1];
        #pragma unroll
        for (int nf = 0; nf < 4; nf++)
          MMAF16(o[mi][nf], pa, vb[kb][nf]);
      }
    }
  }

  #pragma unroll
  for (int mi = 0; mi < 2; mi++){
    #pragma unroll
    for (int hf = 0; hf < 2; hf++){
      float lv = l_[mi][hf];
      lv += __shfl_xor_sync(0xffffffffu, lv, 1);
      lv += __shfl_xor_sync(0xffffffffu, lv, 2);
      float inv = (lv > 0.f) ? (1.0f / lv) : 0.0f;
      const int rg = b*SEQ + n0 + qs*32 + mi*16 + hf*8 + l4;
      #pragma unroll
      for (int nf = 0; nf < 4; nf++){
        float v0 = o[mi][nf][2*hf]*inv;
        float v1 = o[mi][nf][2*hf+1]*inv;
        *(uint32_t*)&ooh[(size_t)rg*DM + head*HDIM + nf*8 + l2] = packh2(v1, v0);
      }
    }
  }
}

// ---------------- launcher --------------------------------------------------
extern "C" void kernel_launch(void* const* d_in, const int* in_sizes, int n_in,
                              void* d_out, int out_size)
{
  const float* x      = (const float*)d_in[0];
  const float* sp     = (const float*)d_in[1];
  const float* ed     = (const float*)d_in[2];
  const float* gamma1 = (const float*)d_in[3];
  const float* beta1  = (const float*)d_in[4];
  const float* gamma2 = (const float*)d_in[5];
  const float* beta2  = (const float*)d_in[6];
  const float* Wq     = (const float*)d_in[7];
  const float* Wk     = (const float*)d_in[8];
  const float* Wv     = (const float*)d_in[9];
  const float* Wo     = (const float*)d_in[10];
  const float* W1     = (const float*)d_in[11];
  const float* b1     = (const float*)d_in[12];
  const float* W2     = (const float*)d_in[13];
  const float* b2     = (const float*)d_in[14];
  float* out = (float*)d_out;

  __half *attin, *ffnin, *qh, *kh, *vh, *oh, *hh, *bsum;
  __half *wq, *wk, *wv, *w2;
  float *attnout;
  int* rowflag;
  cudaGetSymbolAddress((void**)&attin,   g_attin);
  cudaGetSymbolAddress((void**)&ffnin,   g_ffnin);
  cudaGetSymbolAddress((void**)&qh,      g_qh);
  cudaGetSymbolAddress((void**)&kh,      g_kh);
  cudaGetSymbolAddress((void**)&vh,      g_vh);
  cudaGetSymbolAddress((void**)&oh,      g_oh);
  cudaGetSymbolAddress((void**)&attnout, g_attnout);
  cudaGetSymbolAddress((void**)&hh,      g_hh);
  cudaGetSymbolAddress((void**)&rowflag, g_rowflag);
  cudaGetSymbolAddress((void**)&bsum,    g_bsum);
  cudaGetSymbolAddress((void**)&wq, g_wq);
  cudaGetSymbolAddress((void**)&wk, g_wk);
  cudaGetSymbolAddress((void**)&wv, g_wv);
  cudaGetSymbolAddress((void**)&w2, g_w2);

  cudaFuncSetAttribute(gemm_fp16<3>,   cudaFuncAttributeMaxDynamicSharedMemorySize, SMEM_DYN);
  cudaFuncSetAttribute(gemm_fp16<4>,   cudaFuncAttributeMaxDynamicSharedMemorySize, SMEM_DYN);
  cudaFuncSetAttribute(wo_ffn1_kernel, cudaFuncAttributeMaxDynamicSharedMemorySize, SMEM_DYN);
  cudaFuncSetAttribute(attn_mma,       cudaFuncAttributeMaxDynamicSharedMemorySize, ATT_SMEM);

  // 1. prep: bsum + weight conversion + rowflag zero + both LayerNorms
  prep_kernel<<<25344, 256>>>(x, sp, ed, gamma1, beta1, gamma2, beta2,
                              Wq, Wk, Wv, Wo, W1, W2);

  // 2. Q,K,V projections -> fp16 (Q pre-scaled by scale*log2e)
  gemm_fp16<4><<<dim3(2, 128, 3), 256, SMEM_DYN>>>(attin, wq, wk, wv,
                                                   nullptr, nullptr, nullptr, nullptr,
                                                   nullptr, nullptr, nullptr,
                                                   qh, kh, vh, DM, DM);

  // 3. flash attention -> o fp16 (head-split, 2 CTAs/SM)
  attn_mma<<<dim3(SEQ/64, BATCH, 2), 256, ATT_SMEM>>>(bsum, qh, kh, vh, oh);

  // 4. Wo projection (+resid x, rowflag) MERGED with FFN1 (+gelu) —
  //    independent problems, identical per-CTA cost (both K=256)
  wo_ffn1_kernel<<<1280, 256, SMEM_DYN>>>(oh, x, rowflag, attnout,
                                          ffnin, b1, hh);

  // 5. FFN down + b2 + att_output residual + row masking -> final output
  gemm_fp16<3><<<dim3(2, 128, 1), 256, SMEM_DYN>>>(hh, w2, w2, w2,
                                                   b2, attnout, rowflag, nullptr,
                                                   out, out, out,
                                                   nullptr, nullptr, nullptr, DM, FF);
}